// round 15
// baseline (speedup 1.0000x reference)
#include <cuda_runtime.h>
#include <cuda_fp16.h>
#include <cstdint>

// ---------------------------------------------------------------------------
// LoRA multi-task MLP via mma.sync fp16 (plain sm_100 target).
// Round 15: R14 champion GEMM untouched. Launch-graph consolidation:
//  - one convertW3 kernel converts k0,k1,k2 upfront (12 -> 7 graph nodes)
//  - reduceP vectorized (float4, unrolled slab loads)
// ---------------------------------------------------------------------------

#define T_TASKS 8
#define RNK 8
#define M_ROWS 8192

#define BM 128
#define BN 128
#define BK 64                          // K elements per chunk (128 B fp16 rows)
#define STAGES 3
#define TILE_BYTES (128 * 128)         // 16 KB per operand tile
#define STAGE_BYTES (2 * TILE_BYTES)   // A | W = 32 KB
#define SMEM_BYTES (STAGES * STAGE_BYTES)   // 96 KB -> 2 CTAs/SM

// ---- scratch (device globals; no allocation allowed) ----------------------
__device__ __half g_A0[(size_t)M_ROWS * 2048];   // fp16 activations, 32 MB
__device__ __half g_A1[(size_t)M_ROWS * 2048];   // fp16 activations, 32 MB
__device__ __half g_B [(size_t)8 * 1024 * 1024]; // W^T fp16 slabs, 16 MB
__device__ float g_p [M_ROWS * RNK];
__device__ float g_pp[16 * M_ROWS * RNK];        // per-n-block partials

// W slab offsets (halves): w0 = 2048x1024 = 2M, w1 = 2048x2048 = 4M, w2 = 2M
#define W0_OFF 0u
#define W1_OFF (2u * 1024 * 1024)
#define W2_OFF (6u * 1024 * 1024)

// ---------------------------------------------------------------------------
__device__ __forceinline__ uint32_t smem_u32(const void* p) {
    uint32_t a;
    asm("{ .reg .u64 t; cvta.to.shared.u64 t, %1; cvt.u32.u64 %0, t; }"
        : "=r"(a) : "l"(p));
    return a;
}

#define CP_ASYNC16(smem, gptr) \
    asm volatile("cp.async.cg.shared.global [%0], [%1], 16;" \
                 :: "r"(smem), "l"(gptr) : "memory")
#define CP_ASYNC_COMMIT() asm volatile("cp.async.commit_group;" ::: "memory")
#define CP_ASYNC_WAIT(n)  asm volatile("cp.async.wait_group %0;" :: "n"(n) : "memory")

#define LDMATRIX_X4(r0,r1,r2,r3,addr) \
    asm volatile("ldmatrix.sync.aligned.m8n8.x4.shared.b16 {%0,%1,%2,%3}, [%4];" \
        : "=r"(r0),"=r"(r1),"=r"(r2),"=r"(r3) : "r"(addr))

__device__ __forceinline__ void mma_fp16(float* c, const uint32_t* a,
                                         const uint32_t* b) {
    asm volatile(
        "mma.sync.aligned.m16n8k16.row.col.f32.f16.f16.f32 "
        "{%0,%1,%2,%3}, {%4,%5,%6,%7}, {%8,%9}, {%0,%1,%2,%3};"
        : "+f"(c[0]), "+f"(c[1]), "+f"(c[2]), "+f"(c[3])
        : "r"(a[0]), "r"(a[1]), "r"(a[2]), "r"(a[3]), "r"(b[0]), "r"(b[1]));
}

// ---------------------------------------------------------------------------
// Fused layer-0 prep: x fp32 -> A0 fp16 AND P0[m,r] = x·D0[:,r,t].
// ---------------------------------------------------------------------------
__global__ __launch_bounds__(256)
void prep0_kernel(const float* __restrict__ x, const float* __restrict__ D,
                  __half* __restrict__ Ap, float* __restrict__ P)
{
    __shared__ float Ds[RNK][1024];
    const int tid  = threadIdx.x;
    const int wid  = tid >> 5;
    const int lane = tid & 31;
    const int row  = blockIdx.x * 8 + wid;
    const int t    = (blockIdx.x * 8) >> 10;

    for (int idx = tid; idx < 1024 * RNK; idx += 256) {
        int k = idx >> 3, r = idx & 7;
        Ds[r][k] = D[(size_t)k * 64 + r * 8 + t];
    }
    __syncthreads();

    const float4* xr = reinterpret_cast<const float4*>(x + (size_t)row * 1024);
    __half* arow = Ap + (size_t)row * 1024;
    float acc[RNK];
#pragma unroll
    for (int r = 0; r < RNK; ++r) acc[r] = 0.f;
#pragma unroll
    for (int i = 0; i < 8; ++i) {
        int kq = lane + 32 * i;
        float4 v = xr[kq];
        int k = kq << 2;
        union { __half h[4]; uint2 u; } hp;
        hp.h[0] = __float2half(v.x);
        hp.h[1] = __float2half(v.y);
        hp.h[2] = __float2half(v.z);
        hp.h[3] = __float2half(v.w);
        *reinterpret_cast<uint2*>(arow + k) = hp.u;
#pragma unroll
        for (int r = 0; r < RNK; ++r) {
            float4 d = *reinterpret_cast<const float4*>(&Ds[r][k]);
            acc[r] += v.x * d.x + v.y * d.y + v.z * d.z + v.w * d.w;
        }
    }
#pragma unroll
    for (int r = 0; r < RNK; ++r) {
        float v = acc[r];
#pragma unroll
        for (int o = 16; o > 0; o >>= 1) v += __shfl_down_sync(0xffffffffu, v, o);
        if (lane == 0) P[(size_t)row * RNK + r] = v;
    }
}

// ---------------------------------------------------------------------------
// P = sum over 16 slabs of Pp, vectorized float4 (16384 float4 elements).
// ---------------------------------------------------------------------------
__global__ __launch_bounds__(256)
void reduceP_kernel(const float4* __restrict__ Pp, float4* __restrict__ P)
{
    int i = blockIdx.x * 256 + threadIdx.x;      // over 16384
    float4 s = make_float4(0.f, 0.f, 0.f, 0.f);
#pragma unroll
    for (int b = 0; b < 16; ++b) {
        float4 v = Pp[(size_t)b * 16384 + i];
        s.x += v.x; s.y += v.y; s.z += v.z; s.w += v.w;
    }
    P[i] = s;
}

// ---------------------------------------------------------------------------
// One kernel converts all three W's: W[K,N] fp32 -> W^T[N,K] fp16.
// Block ranges: [0,2048) -> k0 (K=1024,N=2048)
//               [2048,6144) -> k1 (K=2048,N=2048)
//               [6144,8192) -> k2 (K=2048,N=1024)
// ---------------------------------------------------------------------------
__global__ __launch_bounds__(256)
void convertW3_kernel(const float* __restrict__ w0,
                      const float* __restrict__ w1,
                      const float* __restrict__ w2,
                      __half* __restrict__ Bbase)
{
    __shared__ float t[32][33];
    int b = blockIdx.x;
    const float* W; __half* Bp; int K, N, bx;
    if (b < 2048)      { W = w0; Bp = Bbase + W0_OFF; K = 1024; N = 2048; bx = b; }
    else if (b < 6144) { W = w1; Bp = Bbase + W1_OFF; K = 2048; N = 2048; bx = b - 2048; }
    else               { W = w2; Bp = Bbase + W2_OFF; K = 2048; N = 1024; bx = b - 6144; }
    const int nBlocksX = N / 32;
    const int n0 = (bx % nBlocksX) * 32;
    const int k0 = (bx / nBlocksX) * 32;

    int tx = threadIdx.x & 31, ty = threadIdx.x >> 5;   // 32 x 8
#pragma unroll
    for (int i = 0; i < 4; ++i)
        t[ty + 8 * i][tx] = W[(size_t)(k0 + ty + 8 * i) * N + n0 + tx];
    __syncthreads();
#pragma unroll
    for (int i = 0; i < 4; ++i) {
        int nn = ty + 8 * i;
        Bp[(size_t)(n0 + nn) * K + k0 + tx] = __float2half(t[tx][nn]);
    }
}

// ---------------------------------------------------------------------------
// 3-stage pipelined fp16 mma.sync GEMM, 2 CTAs/SM, prefetch-before-compute.
//   acc = A*W   (fp32 accumulate)   [byte-identical to R14 champion]
// mode==1: fp16 output (stride N) + ReLU + fused P partials (Dn).
// mode==0: fp32 output (stride N), no ReLU, no P partials.
// ---------------------------------------------------------------------------
__global__ __launch_bounds__(256, 2)
void gemm_mma_kernel(const __half* __restrict__ Ap,
                     const __half* __restrict__ Bp,
                     const float* __restrict__ bias,
                     const float* __restrict__ P,
                     const float* __restrict__ U,
                     void* __restrict__ Cp,
                     const float* __restrict__ Dn,   // next-layer D or null
                     float* __restrict__ Pp,         // partial buffer or null
                     int K, int N, int mode)
{
    extern __shared__ char smem[];
    const uint32_t sbase = smem_u32(smem);
    const int tid  = threadIdx.x;
    const int wid  = tid >> 5;
    const int lane = tid & 31;
    const int mBase = blockIdx.y * BM;
    const int nBase = blockIdx.x * BN;
    const int task  = mBase >> 10;
    const int nChunks = K / BK;

    const int warp_m = (wid >> 2) * 64;   // 0 / 64
    const int warp_n = (wid & 3) * 32;    // 0 / 32 / 64 / 96

    // ---- producer addressing: 4 granules per tile per thread ---------------
    const __half* gA[4];
    const __half* gB[4];
    uint32_t sAB[4];
#pragma unroll
    for (int i = 0; i < 4; ++i) {
        int g = tid + (i << 8);           // 16B granule id 0..1023
        int r = g >> 3, q = g & 7;        // row 0..127, 16B col 0..7
        uint32_t off = (uint32_t)(r << 7) + (q << 4);
        sAB[i] = off ^ ((uint32_t)(r & 7) << 4);
        gA[i] = Ap + (size_t)(mBase + r) * (uint32_t)K + (q << 3);
        gB[i] = Bp + (size_t)(nBase + r) * (uint32_t)K + (q << 3);
    }

    float acc[4][4][4];
#pragma unroll
    for (int mi = 0; mi < 4; ++mi)
#pragma unroll
        for (int ni = 0; ni < 4; ++ni)
#pragma unroll
            for (int j = 0; j < 4; ++j) acc[mi][ni][j] = 0.f;

    // ---- prologue: fill STAGES-1 stages -----------------------------------
#pragma unroll
    for (int c = 0; c < STAGES - 1; ++c) {
        const uint32_t st = sbase + c * STAGE_BYTES;
        const int kc = c * BK;
#pragma unroll
        for (int i = 0; i < 4; ++i) {
            CP_ASYNC16(st + sAB[i],              gA[i] + kc);   // A
            CP_ASYNC16(st + TILE_BYTES + sAB[i], gB[i] + kc);   // W
        }
        CP_ASYNC_COMMIT();
    }

    // ---- ldmatrix addressing ----------------------------------------------
    uint32_t aRow[4], aXm[4];
    const uint32_t aCol = (uint32_t)(lane >> 4) << 4;
#pragma unroll
    for (int mi = 0; mi < 4; ++mi) {
        int r = warp_m + mi * 16 + (lane & 15);
        aRow[mi] = (uint32_t)r << 7;
        aXm[mi]  = (uint32_t)(r & 7) << 4;
    }
    // B paired x4: pair p covers ni = 2p, 2p+1
    uint32_t bRowP[2], bXmP[2];
    const uint32_t bCol = (uint32_t)((lane >> 3) & 1) << 4;
#pragma unroll
    for (int p = 0; p < 2; ++p) {
        int r = warp_n + (2 * p + ((lane >> 4) & 1)) * 8 + (lane & 7);
        bRowP[p] = (uint32_t)r << 7;
        bXmP[p]  = (uint32_t)(r & 7) << 4;
    }

    // ---- mainloop: wait -> sync -> prefetch -> compute ----------------------
    int s = 0;
    for (int c = 0; c < nChunks; ++c) {
        CP_ASYNC_WAIT(STAGES - 2);
        __syncthreads();

        const int cn = c + STAGES - 1;
        if (cn < nChunks) {
            int sn = s + (STAGES - 1); if (sn >= STAGES) sn -= STAGES;
            const uint32_t st = sbase + sn * STAGE_BYTES;
            const int kc = cn * BK;
#pragma unroll
            for (int i = 0; i < 4; ++i) {
                CP_ASYNC16(st + sAB[i],              gA[i] + kc);
                CP_ASYNC16(st + TILE_BYTES + sAB[i], gB[i] + kc);
            }
        }
        CP_ASYNC_COMMIT();

        const uint32_t stA = sbase + s * STAGE_BYTES;
        const uint32_t stB = stA + TILE_BYTES;

#pragma unroll
        for (int kk = 0; kk < 4; ++kk) {
            const uint32_t kb = (uint32_t)kk << 5;
            uint32_t a[4][4], b[4][2];
#pragma unroll
            for (int mi = 0; mi < 4; ++mi) {
                uint32_t xo = (kb + aCol);
                LDMATRIX_X4(a[mi][0], a[mi][1], a[mi][2], a[mi][3],
                            stA + aRow[mi] + (xo ^ aXm[mi]));
            }
#pragma unroll
            for (int p = 0; p < 2; ++p) {
                uint32_t xo = (kb + bCol);
                LDMATRIX_X4(b[2*p][0], b[2*p][1], b[2*p+1][0], b[2*p+1][1],
                            stB + bRowP[p] + (xo ^ bXmP[p]));
            }
#pragma unroll
            for (int mi = 0; mi < 4; ++mi)
#pragma unroll
                for (int ni = 0; ni < 4; ++ni)
                    mma_fp16(acc[mi][ni], a[mi], b[ni]);
        }

        if (++s == STAGES) s = 0;
    }

    // ---- epilogue ----------------------------------------------------------
    CP_ASYNC_WAIT(0);
    __syncthreads();

    float* bias_s = reinterpret_cast<float*>(smem);                // [128]
    float* Us     = reinterpret_cast<float*>(smem + 1024);         // [8][128]
    float* Ps     = reinterpret_cast<float*>(smem + 1024 + 4096);  // [128][8]
    float* Dsn    = reinterpret_cast<float*>(smem + 1024 + 8192);  // [128][8]
    float* sPP    = reinterpret_cast<float*>(smem + 16384);        // [4][128][8]

    if (tid < BN) bias_s[tid] = bias[nBase + tid];
#pragma unroll
    for (int i = 0; i < 4; ++i) {
        int idx = tid + (i << 8);
        int r = idx >> 7, n = idx & 127;
        Us[idx] = U[((size_t)r * N + nBase + n) * T_TASKS + task];
    }
    {
        int row = tid >> 1, half = (tid & 1) << 2;
        float4 v = *reinterpret_cast<const float4*>(
            P + (size_t)(mBase + row) * RNK + half);
        *reinterpret_cast<float4*>(&Ps[row * RNK + half]) = v;
    }
    if (mode == 1) {
#pragma unroll
        for (int i = 0; i < 4; ++i) {
            int idx = tid + (i << 8);
            int n = idx >> 3, r = idx & 7;
            Dsn[idx] = Dn[(size_t)(nBase + n) * 64 + r * 8 + task];
        }
    }
    __syncthreads();

#pragma unroll
    for (int mi = 0; mi < 4; ++mi) {
#pragma unroll
        for (int half = 0; half < 2; ++half) {
            const int rloc = warp_m + mi * 16 + (lane >> 2) + half * 8;
            const int gm   = mBase + rloc;
            float pr[RNK];
            {
                float4 p0 = *reinterpret_cast<const float4*>(&Ps[rloc * RNK]);
                float4 p1 = *reinterpret_cast<const float4*>(&Ps[rloc * RNK + 4]);
                pr[0]=p0.x; pr[1]=p0.y; pr[2]=p0.z; pr[3]=p0.w;
                pr[4]=p1.x; pr[5]=p1.y; pr[6]=p1.z; pr[7]=p1.w;
            }
            float pp[RNK];
#pragma unroll
            for (int r = 0; r < RNK; ++r) pp[r] = 0.f;

#pragma unroll
            for (int ni = 0; ni < 4; ++ni) {
                const int nloc = warp_n + ni * 8 + ((lane & 3) << 1);
                float l0 = 0.f, l1 = 0.f;
#pragma unroll
                for (int q = 0; q < RNK; ++q) {
                    l0 += pr[q] * Us[(q << 7) + nloc];
                    l1 += pr[q] * Us[(q << 7) + nloc + 1];
                }
                float v0 = acc[mi][ni][half * 2 + 0] + bias_s[nloc]     + 2.f * l0;
                float v1 = acc[mi][ni][half * 2 + 1] + bias_s[nloc + 1] + 2.f * l1;
                if (mode == 1) {
                    v0 = fmaxf(v0, 0.f); v1 = fmaxf(v1, 0.f);
                    __half2 hv;
                    hv.x = __float2half(v0);
                    hv.y = __float2half(v1);
                    __half* orow = (__half*)Cp + (size_t)gm * N + nBase + nloc;
                    *reinterpret_cast<__half2*>(orow) = hv;
#pragma unroll
                    for (int r = 0; r < RNK; ++r)
                        pp[r] += v0 * Dsn[(nloc << 3) + r]
                               + v1 * Dsn[((nloc + 1) << 3) + r];
                } else {
                    float* crow = (float*)Cp + (size_t)gm * N + nBase + nloc;
                    *reinterpret_cast<float2*>(crow) = make_float2(v0, v1);
                }
            }

            if (mode == 1) {
                // reduce across the quad (4 lanes share rloc)
#pragma unroll
                for (int r = 0; r < RNK; ++r) {
                    pp[r] += __shfl_xor_sync(0xffffffffu, pp[r], 1);
                    pp[r] += __shfl_xor_sync(0xffffffffu, pp[r], 2);
                }
                if ((lane & 3) == 0) {
                    float* dst = &sPP[(((wid & 3) << 7) + rloc) * RNK];
#pragma unroll
                    for (int r = 0; r < RNK; ++r) dst[r] = pp[r];
                }
            }
        }
    }

    if (mode == 1) {
        __syncthreads();
        for (int i = tid; i < BM * RNK; i += 256) {
            float sum = sPP[i] + sPP[1024 + i] + sPP[2048 + i] + sPP[3072 + i];
            Pp[(size_t)blockIdx.x * (M_ROWS * RNK) + (size_t)mBase * RNK + i] = sum;
        }
    }
}

// ---------------------------------------------------------------------------
// Host launcher: 7 graph nodes.
// ---------------------------------------------------------------------------
extern "C" void kernel_launch(void* const* d_in, const int* in_sizes, int n_in,
                              void* d_out, int out_size)
{
    const float* x  = (const float*)d_in[0];
    const float* k0 = (const float*)d_in[1];
    const float* b0 = (const float*)d_in[2];
    const float* d0 = (const float*)d_in[3];
    const float* u0 = (const float*)d_in[4];
    const float* k1 = (const float*)d_in[5];
    const float* b1 = (const float*)d_in[6];
    const float* d1 = (const float*)d_in[7];
    const float* u1 = (const float*)d_in[8];
    const float* k2 = (const float*)d_in[9];
    const float* b2 = (const float*)d_in[10];
    const float* d2 = (const float*)d_in[11];
    const float* u2 = (const float*)d_in[12];
    float* out = (float*)d_out;

    __half *a0, *a1, *bS;
    float *p, *pp;
    cudaGetSymbolAddress((void**)&a0, g_A0);
    cudaGetSymbolAddress((void**)&a1, g_A1);
    cudaGetSymbolAddress((void**)&bS, g_B);
    cudaGetSymbolAddress((void**)&p,  g_p);
    cudaGetSymbolAddress((void**)&pp, g_pp);

    cudaFuncSetAttribute(gemm_mma_kernel,
                         cudaFuncAttributeMaxDynamicSharedMemorySize, SMEM_BYTES);

    // all weight conversions upfront (one node)
    convertW3_kernel<<<8192, 256>>>(k0, k1, k2, bS);

    // layer-0 prep: x -> A0 fp16 + P0, single pass over x
    prep0_kernel<<<M_ROWS / 8, 256>>>(x, d0, a0, p);

    // layer 0: A0[.,1024] -> A1[.,2048] fp16+ReLU, fused P' partials (d1)
    gemm_mma_kernel<<<dim3(2048 / BN, M_ROWS / BM), 256, SMEM_BYTES>>>(
        a0, bS + W0_OFF, b0, p, u0, a1, d1, pp, 1024, 2048, 1);
    reduceP_kernel<<<64, 256>>>((const float4*)pp, (float4*)p);

    // layer 1: A1[.,2048] -> A0[.,2048] fp16+ReLU, fused P' partials (d2)
    gemm_mma_kernel<<<dim3(2048 / BN, M_ROWS / BM), 256, SMEM_BYTES>>>(
        a1, bS + W1_OFF, b1, p, u1, a0, d2, pp, 2048, 2048, 1);
    reduceP_kernel<<<64, 256>>>((const float4*)pp, (float4*)p);

    // layer 2: A0[.,2048] -> out fp32 [.,1024], no ReLU
    gemm_mma_kernel<<<dim3(1024 / BN, M_ROWS / BM), 256, SMEM_BYTES>>>(
        a0, bS + W2_OFF, b2, p, u2, out, nullptr, nullptr, 2048, 1024, 0);
}